// round 5
// baseline (speedup 1.0000x reference)
#include <cuda_runtime.h>
#include <cuda_bf16.h>

// RotatedIoULoss: per-pair rotated-box IoU, loss = mean(-log(max(iou,1e-6))).
//
// Target-local-frame clipping: target becomes the axis-aligned rect
// [-hwt,hwt] x [-hht,hht]. The pred quad is clipped by the x-SLAB (both
// vertical planes in one traversal) then the y-SLAB. Slab clipping of a
// convex polygon is exact: the two parallel planes cut disjoint caps, each
// replaced by a chord; per-edge emission ordered by t reproduces boundary
// order. One fast reciprocal per edge serves both planes; intersection
// points have their clipped coordinate exactly at +/-bound.
// Branchless emission: unconditional store + predicated index increment
// (avoids BSSY/BSYNC and divergence serialization).
// Fast-math __fdividef/__logf/__sincosf (500k-mean tolerance absorbs error).
// Deterministic two-stage reduction, graph-capturable, allocation-free.

#define THREADS 256
#define MAX_BLOCKS 4096

__device__ float g_block_sums[MAX_BLOCKS];

struct Pt { float x, y; };

__global__ void __launch_bounds__(THREADS)
rot_iou_loss_kernel(const float* __restrict__ pred,
                    const float* __restrict__ target, int n) {
    float acc = 0.f;

    for (int i = blockIdx.x * blockDim.x + threadIdx.x; i < n;
         i += gridDim.x * blockDim.x) {
        const float px = pred[i * 5 + 0], py = pred[i * 5 + 1];
        const float pw = pred[i * 5 + 2], ph = pred[i * 5 + 3];
        const float pa = pred[i * 5 + 4];
        const float tx = target[i * 5 + 0], ty = target[i * 5 + 1];
        const float tw = target[i * 5 + 2], th = target[i * 5 + 3];
        const float ta = target[i * 5 + 4];

        // Target local frame: rotate by -ta about (tx,ty).
        float st, ct;
        __sincosf(ta, &st, &ct);
        const float dx = px - tx, dy = py - ty;
        const float lx =  dx * ct + dy * st;
        const float ly = -dx * st + dy * ct;

        // Pred quad corners in that frame (rotation = pa - ta), CCW.
        float sd, cd;
        __sincosf(pa - ta, &sd, &cd);
        const float hwp = 0.5f * pw, hhp = 0.5f * ph;
        const float cx = cd * hwp, sx = sd * hwp;
        const float cy = cd * hhp, sy = sd * hhp;

        Pt c0, c1, c2, c3;
        c0.x = lx - cx + sy;  c0.y = ly - sx - cy;
        c1.x = lx + cx + sy;  c1.y = ly + sx - cy;
        c2.x = lx + cx - sy;  c2.y = ly + sx + cy;
        c3.x = lx - cx - sy;  c3.y = ly - sx + cy;

        const float hwt = 0.5f * tw, hht = 0.5f * th;

        // ---------- Pass A: clip by x-slab |x| <= hwt  (registers -> b) ----
        Pt b[8];
        int m = 0;
        {
            Pt cs[4] = {c0, c1, c2, c3};
            Pt P = c3;
            bool il_p = (P.x >= -hwt);
            bool ir_p = (P.x <=  hwt);
            #pragma unroll
            for (int k = 0; k < 4; ++k) {
                Pt C = cs[k];
                bool il_c = (C.x >= -hwt);
                bool ir_c = (C.x <=  hwt);

                b[m] = P;                       // emit P if inside slab
                m += (int)(il_p && ir_p);

                float r  = __fdividef(1.f, C.x - P.x);
                float dyv = C.y - P.y;
                float tl = (-hwt - P.x) * r;
                float tr = ( hwt - P.x) * r;
                Pt pl; pl.x = -hwt; pl.y = fmaf(tl, dyv, P.y);
                Pt pr; pr.x =  hwt; pr.y = fmaf(tr, dyv, P.y);

                bool cl = (il_p != il_c);
                bool cr = (ir_p != ir_c);
                bool both = cl && cr;
                bool lfirst = tl < tr;

                Pt pA = both ? (lfirst ? pl : pr) : (cl ? pl : pr);
                Pt pB = lfirst ? pr : pl;

                b[m] = pA;  m += (int)(cl || cr);
                b[m] = pB;  m += (int)both;

                P = C; il_p = il_c; ir_p = ir_c;
            }
        }

        // ---------- Pass B: clip by y-slab |y| <= hht  (b -> a) ------------
        Pt a[10];
        int mo = 0;
        if (m >= 3) {
            Pt P = b[m - 1];
            bool ib_p = (P.y >= -hht);
            bool it_p = (P.y <=  hht);
            #pragma unroll 1
            for (int k = 0; k < m; ++k) {
                Pt C = b[k];
                bool ib_c = (C.y >= -hht);
                bool it_c = (C.y <=  hht);

                a[mo] = P;
                mo += (int)(ib_p && it_p);

                float r  = __fdividef(1.f, C.y - P.y);
                float dxv = C.x - P.x;
                float tb = (-hht - P.y) * r;
                float tt = ( hht - P.y) * r;
                Pt pb; pb.y = -hht; pb.x = fmaf(tb, dxv, P.x);
                Pt pt; pt.y =  hht; pt.x = fmaf(tt, dxv, P.x);

                bool cb = (ib_p != ib_c);
                bool ctp = (it_p != it_c);
                bool both = cb && ctp;
                bool bfirst = tb < tt;

                Pt pA = both ? (bfirst ? pb : pt) : (cb ? pb : pt);
                Pt pB = bfirst ? pt : pb;

                a[mo] = pA;  mo += (int)(cb || ctp);
                a[mo] = pB;  mo += (int)both;

                P = C; ib_p = ib_c; it_p = it_c;
            }
        }

        // ---------- Shoelace over a[0..mo) --------------------------------
        float s2 = 0.f;
        if (mo >= 3) {
            Pt P = a[mo - 1];
            #pragma unroll 1
            for (int k = 0; k < mo; ++k) {
                Pt C = a[k];
                s2 = fmaf(P.x, C.y, s2);
                s2 = fmaf(-P.y, C.x, s2);
                P = C;
            }
        }

        const float area_i = 0.5f * fabsf(s2);
        const float a1 = pw * ph;
        const float a2 = tw * th;
        const float denom = fmaxf(a1 + a2 - area_i, 1e-10f);
        float iou = fmaxf(__fdividef(area_i, denom), 1e-6f);
        acc -= __logf(iou);
    }

    // Block tree reduction.
    __shared__ float sh[THREADS];
    sh[threadIdx.x] = acc;
    __syncthreads();
    #pragma unroll
    for (int k = THREADS / 2; k > 32; k >>= 1) {
        if (threadIdx.x < k) sh[threadIdx.x] += sh[threadIdx.x + k];
        __syncthreads();
    }
    if (threadIdx.x < 32) {
        float vsum = sh[threadIdx.x] + sh[threadIdx.x + 32];
        #pragma unroll
        for (int o = 16; o > 0; o >>= 1)
            vsum += __shfl_down_sync(0xffffffffu, vsum, o);
        if (threadIdx.x == 0) g_block_sums[blockIdx.x] = vsum;
    }
}

__global__ void __launch_bounds__(1024)
final_reduce_kernel(float* __restrict__ out, int nblocks, float inv_n) {
    __shared__ float sh[1024];
    float s = 0.f;
    for (int i = threadIdx.x; i < nblocks; i += 1024) s += g_block_sums[i];
    sh[threadIdx.x] = s;
    __syncthreads();
    #pragma unroll
    for (int k = 512; k > 32; k >>= 1) {
        if (threadIdx.x < k) sh[threadIdx.x] += sh[threadIdx.x + k];
        __syncthreads();
    }
    if (threadIdx.x < 32) {
        float v = sh[threadIdx.x] + sh[threadIdx.x + 32];
        #pragma unroll
        for (int o = 16; o > 0; o >>= 1)
            v += __shfl_down_sync(0xffffffffu, v, o);
        if (threadIdx.x == 0) out[0] = v * inv_n;
    }
}

extern "C" void kernel_launch(void* const* d_in, const int* in_sizes, int n_in,
                              void* d_out, int out_size) {
    const float* pred   = (const float*)d_in[0];
    const float* target = (const float*)d_in[1];
    float* out = (float*)d_out;

    const int n = in_sizes[0] / 5;
    int blocks = (n + THREADS - 1) / THREADS;
    if (blocks > MAX_BLOCKS) blocks = MAX_BLOCKS;
    if (blocks < 1) blocks = 1;

    rot_iou_loss_kernel<<<blocks, THREADS>>>(pred, target, n);
    final_reduce_kernel<<<1, 1024>>>(out, blocks, 1.0f / (float)n);
}